// round 16
// baseline (speedup 1.0000x reference)
#include <cuda_runtime.h>
#include <cuda_bf16.h>
#include <math.h>
#include <complex>
#include <algorithm>

// Problem: RS=[(16,0),(16,1)] -> N_DIM=64, N_PATH=1536, RADIAL_H=64
// points = 16*32*32 = 16384; out = points * 64*64 fp32.

#define NPOINTS 16384
#define GPTS    8
#define NBLK    (NPOINTS / GPTS)
#define NPATH   1536
#define NTHREADS 256

struct Consts {
    float cg000;
    float cg011[3][3];   // real3j(0,1,1)[0][j][k]
    float cg101[3][3];   // real3j(1,0,1)[i][0][k]
    float cg110[3][3];   // real3j(1,1,0)[i][j][0]
    float cg111[3][3][3];
    float cg112[3][3][5];
    float nrm[2][2][2];
};

// W2 permuted, s-pair packed over k-pairs (NO duplication, 384 KB):
// float index o = (((sp*32 + k2)*256 + t)*4 + e)
//   e=0: (k=2k2  , s=2sp  )   e=1: (k=2k2  , s=2sp+1)
//   e=2: (k=2k2+1, s=2sp  )   e=3: (k=2k2+1, s=2sp+1)
// col(s,t) = s<3 ? s*256+t : 768+3t+(s-3)
__device__ float g_W2P[64 * NPATH];

__global__ void permute_w2(const float* __restrict__ W2) {
    int o = blockIdx.x * blockDim.x + threadIdx.x;
    if (o >= 64 * NPATH) return;
    int e  = o & 3;
    int t  = (o >> 2) & 255;
    int k2 = (o >> 10) & 31;
    int sp = o >> 15;
    int k  = 2 * k2 + (e >> 1);
    int s  = 2 * sp + (e & 1);
    int col = (s < 3) ? (s * 256 + t) : (768 + 3 * t + (s - 3));
    g_W2P[o] = W2[k * NPATH + col];
}

__device__ __forceinline__ unsigned long long fma2(unsigned long long a,
                                                   unsigned long long b,
                                                   unsigned long long c) {
    unsigned long long d;
    asm("fma.rn.f32x2 %0, %1, %2, %3;" : "=l"(d) : "l"(a), "l"(b), "l"(c));
    return d;
}
__device__ __forceinline__ void unpack2(unsigned long long v, float& lo, float& hi) {
    asm("mov.b64 {%0, %1}, %2;" : "=f"(lo), "=f"(hi) : "l"(v));
}
__device__ __forceinline__ void stg_cs(float4* p, float4 v) {
    asm volatile("st.global.cs.v4.f32 [%0], {%1, %2, %3, %4};"
                 :: "l"(p), "f"(v.x), "f"(v.y), "f"(v.z), "f"(v.w) : "memory");
}

// Dynamic smem layout (bytes), per 256-thread CTA (8 points):
//   [0, 49152)       sR: float[6][8][256]   ((s*8+p)*256 + tc)
//   [49152, 53248)   sh_hd: float2[64][8]   (h duplicated)
//   [53248, 54400)   sh_pp: float[8][36]
//   [54400, 54432)   sh_rad: float[8]
#define OFF_HD  49152
#define OFF_PP  53248
#define OFF_RAD 54400
#define SMEM_TOTAL 54432

__global__ __launch_bounds__(NTHREADS, 2)
void qm9_fused(const float* __restrict__ r,
               const float* __restrict__ W1,
               const float* __restrict__ b1,
               const float* __restrict__ b2,
               float* __restrict__ out,
               const Consts C)
{
    extern __shared__ __align__(16) char smem[];
    float* sR           = (float*)smem;                 // [(s*8+p)*256 + tc]
    float2 (*sh_hd)[8]  = (float2(*)[8])(smem + OFF_HD);
    float (*sh_pp)[36]  = (float(*)[36])(smem + OFF_PP);
    float* sh_rad       = (float*)(smem + OFF_RAD);

    const int t = threadIdx.x;   // 0..255 — column owner, owns ALL 6 s
    const int block0 = blockIdx.x * GPTS;

    // ---- Phase A: per-point SH + folded CG*Y*norm (threads 0..7) ----
    if (t < GPTS) {
        int pg = block0 + t;
        float x = r[pg * 3 + 0], y = r[pg * 3 + 1], z = r[pg * 3 + 2];
        float r2 = x * x + y * y + z * z;
        sh_rad[t] = sqrtf(r2);
        float inv  = rsqrtf(r2);
        float inv2 = 1.0f / r2;
        const float c0  = 0.28209479177387814f;
        const float c1  = 0.48860251190291992f;
        const float c2  = 1.09254843059207907f;
        const float c20 = 0.31539156525252005f;
        float Y[9];
        Y[0] = c0;
        Y[1] = c1 * y * inv;
        Y[2] = c1 * z * inv;
        Y[3] = c1 * x * inv;
        Y[4] = c2 * x * y * inv2;
        Y[5] = c2 * y * z * inv2;
        Y[6] = c20 * (3.0f * z * z - r2) * inv2;
        Y[7] = c2 * x * z * inv2;
        Y[8] = 0.5f * c2 * (x * x - y * y) * inv2;

        int zf = (r2 == 0.0f) ? 1 : 0;
        float s00 = C.nrm[0][0][zf], s01 = C.nrm[0][1][zf];
        float s10 = C.nrm[1][0][zf], s11 = C.nrm[1][1][zf];

        sh_pp[t][0] = C.cg000 * Y[0] * s00;
        #pragma unroll
        for (int j = 0; j < 3; j++) {
            float a = 0.f;
            #pragma unroll
            for (int k = 0; k < 3; k++) a += C.cg011[j][k] * Y[1 + k];
            sh_pp[t][1 + j] = a * s01;
        }
        #pragma unroll
        for (int i = 0; i < 3; i++) {
            float a = 0.f;
            #pragma unroll
            for (int k = 0; k < 3; k++) a += C.cg101[i][k] * Y[1 + k];
            sh_pp[t][4 + i] = a * s10;
        }
        #pragma unroll
        for (int i = 0; i < 3; i++) {
            #pragma unroll
            for (int j = 0; j < 3; j++) {
                sh_pp[t][7 + i * 3 + j] = C.cg110[i][j] * Y[0] * s11;
                float a1 = 0.f;
                #pragma unroll
                for (int k = 0; k < 3; k++) a1 += C.cg111[i][j][k] * Y[1 + k];
                sh_pp[t][16 + i * 3 + j] = a1 * s11;
                float a2 = 0.f;
                #pragma unroll
                for (int k = 0; k < 5; k++) a2 += C.cg112[i][j][k] * Y[4 + k];
                sh_pp[t][25 + i * 3 + j] = a2 * s11;
            }
        }
    }
    __syncthreads();

    // ---- Phase B: h = silu(rad*W1+b1), stored duplicated (h,h) ----
    {
        int p  = t & 7;
        int k0 = (t >> 3) * 2;   // t>>3 in 0..31 -> k0 in 0..62
        float rad = sh_rad[p];
        #pragma unroll
        for (int e = 0; e < 2; e++) {
            float xx = fmaf(rad, W1[k0 + e], b1[k0 + e]);
            float h = xx / (1.0f + expf(-xx));
            sh_hd[k0 + e][p] = make_float2(h, h);
        }
    }

    // b2 loads hoisted (hidden under Phase B + barrier).
    float b2v[6];
    #pragma unroll
    for (int s = 0; s < 6; s++)
        b2v[s] = b2[(s < 3) ? (s * 256 + t) : (768 + 3 * t + (s - 3))];
    __syncthreads();

    // ---- Phase C: f32x2 GEMM over s-pairs, 8 points, zero packs ----
    unsigned long long acc[8][3];   // acc[p][sp] = (R_{2sp}(p), R_{2sp+1}(p))
    #pragma unroll
    for (int p = 0; p < 8; p++)
        #pragma unroll
        for (int sp = 0; sp < 3; sp++) acc[p][sp] = 0ull;

    const ulonglong2* wp = (const ulonglong2*)g_W2P + t;   // slot stride 256
    const unsigned long long* hrow = (const unsigned long long*)sh_hd;  // [k*8 + p]

    ulonglong2 wA = wp[(0 * 32 + 0) * 256];
    ulonglong2 wB = wp[(1 * 32 + 0) * 256];
    ulonglong2 wC = wp[(2 * 32 + 0) * 256];

    #pragma unroll 1
    for (int k2 = 0; k2 < 32; k2++) {
        int kn = (k2 < 31) ? (k2 + 1) : 31;
        ulonglong2 nA = wp[(0 * 32 + kn) * 256];
        ulonglong2 nB = wp[(1 * 32 + kn) * 256];
        ulonglong2 nC = wp[(2 * 32 + kn) * 256];

        const ulonglong2* he2 = (const ulonglong2*)&hrow[(2 * k2 + 0) * 8];
        const ulonglong2* ho2 = (const ulonglong2*)&hrow[(2 * k2 + 1) * 8];
        ulonglong2 heA = he2[0], heB = he2[1], heC = he2[2], heD = he2[3];
        ulonglong2 hoA = ho2[0], hoB = ho2[1], hoC = ho2[2], hoD = ho2[3];

        // k even (wX.x holds (s_even, s_odd) for k=2k2)
        acc[0][0] = fma2(heA.x, wA.x, acc[0][0]);
        acc[0][1] = fma2(heA.x, wB.x, acc[0][1]);
        acc[0][2] = fma2(heA.x, wC.x, acc[0][2]);
        acc[1][0] = fma2(heA.y, wA.x, acc[1][0]);
        acc[1][1] = fma2(heA.y, wB.x, acc[1][1]);
        acc[1][2] = fma2(heA.y, wC.x, acc[1][2]);
        acc[2][0] = fma2(heB.x, wA.x, acc[2][0]);
        acc[2][1] = fma2(heB.x, wB.x, acc[2][1]);
        acc[2][2] = fma2(heB.x, wC.x, acc[2][2]);
        acc[3][0] = fma2(heB.y, wA.x, acc[3][0]);
        acc[3][1] = fma2(heB.y, wB.x, acc[3][1]);
        acc[3][2] = fma2(heB.y, wC.x, acc[3][2]);
        acc[4][0] = fma2(heC.x, wA.x, acc[4][0]);
        acc[4][1] = fma2(heC.x, wB.x, acc[4][1]);
        acc[4][2] = fma2(heC.x, wC.x, acc[4][2]);
        acc[5][0] = fma2(heC.y, wA.x, acc[5][0]);
        acc[5][1] = fma2(heC.y, wB.x, acc[5][1]);
        acc[5][2] = fma2(heC.y, wC.x, acc[5][2]);
        acc[6][0] = fma2(heD.x, wA.x, acc[6][0]);
        acc[6][1] = fma2(heD.x, wB.x, acc[6][1]);
        acc[6][2] = fma2(heD.x, wC.x, acc[6][2]);
        acc[7][0] = fma2(heD.y, wA.x, acc[7][0]);
        acc[7][1] = fma2(heD.y, wB.x, acc[7][1]);
        acc[7][2] = fma2(heD.y, wC.x, acc[7][2]);
        // k odd
        acc[0][0] = fma2(hoA.x, wA.y, acc[0][0]);
        acc[0][1] = fma2(hoA.x, wB.y, acc[0][1]);
        acc[0][2] = fma2(hoA.x, wC.y, acc[0][2]);
        acc[1][0] = fma2(hoA.y, wA.y, acc[1][0]);
        acc[1][1] = fma2(hoA.y, wB.y, acc[1][1]);
        acc[1][2] = fma2(hoA.y, wC.y, acc[1][2]);
        acc[2][0] = fma2(hoB.x, wA.y, acc[2][0]);
        acc[2][1] = fma2(hoB.x, wB.y, acc[2][1]);
        acc[2][2] = fma2(hoB.x, wC.y, acc[2][2]);
        acc[3][0] = fma2(hoB.y, wA.y, acc[3][0]);
        acc[3][1] = fma2(hoB.y, wB.y, acc[3][1]);
        acc[3][2] = fma2(hoB.y, wC.y, acc[3][2]);
        acc[4][0] = fma2(hoC.x, wA.y, acc[4][0]);
        acc[4][1] = fma2(hoC.x, wB.y, acc[4][1]);
        acc[4][2] = fma2(hoC.x, wC.y, acc[4][2]);
        acc[5][0] = fma2(hoC.y, wA.y, acc[5][0]);
        acc[5][1] = fma2(hoC.y, wB.y, acc[5][1]);
        acc[5][2] = fma2(hoC.y, wC.y, acc[5][2]);
        acc[6][0] = fma2(hoD.x, wA.y, acc[6][0]);
        acc[6][1] = fma2(hoD.x, wB.y, acc[6][1]);
        acc[6][2] = fma2(hoD.x, wC.y, acc[6][2]);
        acc[7][0] = fma2(hoD.y, wA.y, acc[7][0]);
        acc[7][1] = fma2(hoD.y, wB.y, acc[7][1]);
        acc[7][2] = fma2(hoD.y, wC.y, acc[7][2]);

        wA = nA; wB = nB; wC = nC;
    }

    // ---- Exchange: acc[p][sp] = (R_{2sp}, R_{2sp+1}) for point p ----
    #pragma unroll
    for (int p = 0; p < 8; p++) {
        #pragma unroll
        for (int sp = 0; sp < 3; sp++) {
            float lo, hi;
            unpack2(acc[p][sp], lo, hi);
            sR[((2 * sp + 0) * 8 + p) * 256 + t] = lo + b2v[2 * sp + 0];
            sR[((2 * sp + 1) * 8 + p) * 256 + t] = hi + b2v[2 * sp + 1];
        }
    }
    __syncthreads();   // single epilogue barrier

    // ---- Phase D: coalesced store phase (R13/R15 body, 8 points) ----
    const int tu = t >> 4;      // 0..15
    const int c  = t & 15;      // col chunk

    int vd0 = 0, vd1 = 0, vd2 = 0, vd3 = 0, jd0 = 0, jd1 = 0, jd2 = 0, jd3 = 0;
    if (c >= 4) {
        int base = 4 * (c - 4);
        vd0 = (base + 0) / 3; jd0 = (base + 0) - 3 * vd0;
        vd1 = (base + 1) / 3; jd1 = (base + 1) - 3 * vd1;
        vd2 = (base + 2) / 3; jd2 = (base + 2) - 3 * vd2;
        vd3 = (base + 3) / 3; jd3 = (base + 3) - 3 * vd3;
    }
    int um[4], im[4];
    #pragma unroll
    for (int m = 1; m < 4; m++) {
        int rr = (m - 1) * 16 + tu;
        um[m] = rr / 3;
        im[m] = rr - 3 * um[m];
    }

    #pragma unroll 1
    for (int p = 0; p < GPTS; p++) {
        const float* pp = sh_pp[p];
        float* o = out + (size_t)(block0 + p) * 4096;
        float4* o4 = (float4*)o;

        #pragma unroll
        for (int m = 0; m < 4; m++) {
            float v0, v1, v2, v3;
            if (m == 0) {
                if (c < 4) {
                    const float* s0 = &sR[(0 * 8 + p) * 256 + tu * 16 + 4 * c];
                    float sc = pp[0];
                    v0 = sc * s0[0]; v1 = sc * s0[1]; v2 = sc * s0[2]; v3 = sc * s0[3];
                } else {
                    const float* s1 = &sR[(1 * 8 + p) * 256 + tu * 16];
                    v0 = pp[1 + jd0] * s1[vd0];
                    v1 = pp[1 + jd1] * s1[vd1];
                    v2 = pp[1 + jd2] * s1[vd2];
                    v3 = pp[1 + jd3] * s1[vd3];
                }
            } else {
                int u2 = um[m], i = im[m];
                if (c < 4) {
                    const float* s2 = &sR[(2 * 8 + p) * 256 + u2 * 16 + 4 * c];
                    float sc = pp[4 + i];
                    v0 = sc * s2[0]; v1 = sc * s2[1]; v2 = sc * s2[2]; v3 = sc * s2[3];
                } else {
                    const float* s3 = &sR[(3 * 8 + p) * 256 + u2 * 16];
                    const float* s4 = &sR[(4 * 8 + p) * 256 + u2 * 16];
                    const float* s5 = &sR[(5 * 8 + p) * 256 + u2 * 16];
                    const float* pa = pp + 7  + 3 * i;
                    const float* pb = pp + 16 + 3 * i;
                    const float* pc = pp + 25 + 3 * i;
                    v0 = pa[jd0] * s3[vd0] + pb[jd0] * s4[vd0] + pc[jd0] * s5[vd0];
                    v1 = pa[jd1] * s3[vd1] + pb[jd1] * s4[vd1] + pc[jd1] * s5[vd1];
                    v2 = pa[jd2] * s3[vd2] + pb[jd2] * s4[vd2] + pc[jd2] * s5[vd2];
                    v3 = pa[jd3] * s3[vd3] + pb[jd3] * s4[vd3] + pc[jd3] * s5[vd3];
                }
            }
            stg_cs(o4 + m * 256 + t, make_float4(v0, v1, v2, v3));
        }
    }
}

// ===========================================================================
// Host: exact replication of the reference real-3j / norm constants.
// ===========================================================================
static double dfact_(int n) { double r = 1.0; for (int i = 2; i <= n; i++) r *= i; return r; }

static double su2_cg_(int j1, int m1, int j2, int m2, int j3, int m3) {
    if (m3 != m1 + m2) return 0.0;
    int vmin = std::max(std::max(-j1 + j2 + m3, -j1 + m1), 0);
    int vmax = std::min(std::min(j2 + j3 + m1, j3 - j1 + j2), j3 + m3);
    double c = sqrt((2 * j3 + 1) * dfact_(j3 + j1 - j2) * dfact_(j3 - j1 + j2) *
                    dfact_(j1 + j2 - j3) / dfact_(j1 + j2 + j3 + 1)) *
               sqrt(dfact_(j3 + m3) * dfact_(j3 - m3) /
                    (dfact_(j1 + m1) * dfact_(j1 - m1) * dfact_(j2 + m2) * dfact_(j2 - m2)));
    double s = 0.0;
    for (int v = vmin; v <= vmax; v++) {
        double sg = ((v + j2 + m2) & 1) ? -1.0 : 1.0;
        s += sg * dfact_(j2 + j3 + m1 - v) * dfact_(j1 - m1 + v) /
             (dfact_(v) * dfact_(j3 - j1 + j2 - v) * dfact_(j3 + m3 - v) *
              dfact_(v + j1 - j2 - m3));
    }
    return c * s;
}

static void Qmat_(int l, std::complex<double> q[5][5]) {
    for (int i = 0; i < 5; i++) for (int j = 0; j < 5; j++) q[i][j] = 0.0;
    q[l][l] = 1.0;
    double s2 = 1.0 / sqrt(2.0);
    for (int m = 1; m <= l; m++) {
        double pm = (m & 1) ? -1.0 : 1.0;
        q[l + m][l - m] = s2;
        q[l + m][l + m] = pm * s2;
        q[l - m][l - m] = std::complex<double>(0.0, s2);
        q[l - m][l + m] = std::complex<double>(0.0, -pm * s2);
    }
}

static void real3j_(int l1, int l2, int l3, double outc[5][5][5]) {
    int d1 = 2 * l1 + 1, d2 = 2 * l2 + 1, d3 = 2 * l3 + 1;
    double w[5][5][5];
    for (int i = 0; i < 5; i++) for (int j = 0; j < 5; j++) for (int k = 0; k < 5; k++)
        w[i][j][k] = 0.0;
    for (int m1 = -l1; m1 <= l1; m1++)
        for (int m2 = -l2; m2 <= l2; m2++) {
            int m3 = -(m1 + m2);
            if (m3 < -l3 || m3 > l3) continue;
            double sg = ((l1 - l2 + m1 + m2) & 1) ? -1.0 : 1.0;
            w[m1 + l1][m2 + l2][m3 + l3] =
                sg / sqrt((double)(2 * l3 + 1)) * su2_cg_(l1, m1, l2, m2, l3, -m3);
        }
    std::complex<double> q1[5][5], q2[5][5], q3[5][5];
    Qmat_(l1, q1); Qmat_(l2, q2); Qmat_(l3, q3);
    std::complex<double> Cc[5][5][5];
    for (int a = 0; a < d1; a++)
        for (int b = 0; b < d2; b++)
            for (int c = 0; c < d3; c++) {
                std::complex<double> s = 0.0;
                for (int i = 0; i < d1; i++)
                    for (int j = 0; j < d2; j++)
                        for (int k = 0; k < d3; k++)
                            s += q1[a][i] * q2[b][j] * q3[c][k] * w[i][j][k];
                Cc[a][b][c] = s;
            }
    double maxv = 0.0;
    for (int a = 0; a < d1; a++) for (int b = 0; b < d2; b++) for (int c = 0; c < d3; c++)
        maxv = std::max(maxv, std::abs(Cc[a][b][c]));
    std::complex<double> ph = 0.0;
    for (int a = 0; a < d1 && ph == 0.0; a++)
        for (int b = 0; b < d2 && ph == 0.0; b++)
            for (int c = 0; c < d3 && ph == 0.0; c++)
                if (std::abs(Cc[a][b][c]) >= maxv * (1.0 - 1e-9)) ph = Cc[a][b][c];
    for (int i = 0; i < 5; i++) for (int j = 0; j < 5; j++) for (int k = 0; k < 5; k++)
        outc[i][j][k] = 0.0;
    if (std::abs(ph) < 1e-12) {
        for (int a = 0; a < d1; a++) for (int b = 0; b < d2; b++) for (int c = 0; c < d3; c++)
            outc[a][b][c] = Cc[a][b][c].real();
    } else {
        std::complex<double> u = ph / std::abs(ph);
        for (int a = 0; a < d1; a++) for (int b = 0; b < d2; b++) for (int c = 0; c < d3; c++)
            outc[a][b][c] = (Cc[a][b][c] / u).real();
    }
}

extern "C" void kernel_launch(void* const* d_in, const int* in_sizes, int n_in,
                              void* d_out, int out_size) {
    const float* r  = (const float*)d_in[0];
    const float* W1 = (const float*)d_in[1];
    const float* b1 = (const float*)d_in[2];
    const float* W2 = (const float*)d_in[3];
    const float* b2 = (const float*)d_in[4];
    float* out = (float*)d_out;

    Consts C;
    double tmp[5][5][5];
    real3j_(0, 0, 0, tmp); C.cg000 = (float)tmp[0][0][0];
    real3j_(0, 1, 1, tmp);
    for (int j = 0; j < 3; j++) for (int k = 0; k < 3; k++) C.cg011[j][k] = (float)tmp[0][j][k];
    real3j_(1, 0, 1, tmp);
    for (int i = 0; i < 3; i++) for (int k = 0; k < 3; k++) C.cg101[i][k] = (float)tmp[i][0][k];
    real3j_(1, 1, 0, tmp);
    for (int i = 0; i < 3; i++) for (int j = 0; j < 3; j++) C.cg110[i][j] = (float)tmp[i][j][0];
    real3j_(1, 1, 1, tmp);
    for (int i = 0; i < 3; i++) for (int j = 0; j < 3; j++) for (int k = 0; k < 3; k++)
        C.cg111[i][j][k] = (float)tmp[i][j][k];
    real3j_(1, 1, 2, tmp);
    for (int i = 0; i < 3; i++) for (int j = 0; j < 3; j++) for (int k = 0; k < 5; k++)
        C.cg112[i][j][k] = (float)tmp[i][j][k];

    const double fourpi = 4.0 * M_PI;
    double nse[2] = {32.0, 64.0};
    for (int i = 0; i < 2; i++)
        for (int j = 0; j < 2; j++) {
            double li = (j == 0) ? 0.0 : 1.0;
            double lm = sqrt(2.0 * li + 1.0) * sqrt(fourpi);
            C.nrm[i][j][0] = (float)(lm / sqrt(nse[i]));
            C.nrm[i][j][1] = (float)(lm / sqrt(16.0));
        }

    cudaFuncSetAttribute(qm9_fused, cudaFuncAttributeMaxDynamicSharedMemorySize,
                         SMEM_TOTAL);

    permute_w2<<<(64 * NPATH + 255) / 256, 256>>>(W2);
    qm9_fused<<<NBLK, NTHREADS, SMEM_TOTAL>>>(r, W1, b1, b2, out, C);
}